// round 8
// baseline (speedup 1.0000x reference)
#include <cuda_runtime.h>
#include <cuda_bf16.h>
#include <cstdint>

// Problem constants
#define U_DIM 20000
#define I_DIM 10000
#define K_DIM 64
#define B_DIM 4096

// Output regions (floats), reference return order.
#define OFF_SHAT   0LL
#define N_SHAT     (200000000LL)                 // U*I
#define OFF_UF     (OFF_SHAT + N_SHAT)           // 200,000,000
#define N_UF       (1280000LL)
#define OFF_UB     (OFF_UF + N_UF)               // 201,280,000
#define N_UB       (20000LL)
#define OFF_IF     (OFF_UB + N_UB)               // 201,300,000
#define N_IF       (640000LL)
#define OFF_IB     (OFF_IF + N_IF)               // 201,940,000
#define N_IB       (10000LL)
#define N_TOTAL    (OFF_IB + N_IB)               // 201,950,000 (divisible by 4)

// ---------------------------------------------------------------------------
// Kernel 1: zero the whole output. PURE fire-and-forget float4 stores — no
// loads, no fences, no atomics (proven 7.27 TB/s). The PDL trigger after the
// store lets the scatter kernel's prologue start while our stores drain.
// ---------------------------------------------------------------------------
__global__ void mmf_zero_kernel(float4* __restrict__ out, long long n4) {
    long long idx = (long long)blockIdx.x * blockDim.x + threadIdx.x;
    if (idx < n4) {
        out[idx] = make_float4(0.f, 0.f, 0.f, 0.f);
    }
    cudaTriggerProgrammaticLaunchCompletion();
}

__device__ __forceinline__ float warp_sum(float s) {
    #pragma unroll
    for (int off = 16; off; off >>= 1)
        s += __shfl_xor_sync(0xffffffffu, s, off);
    return s;
}

// ---------------------------------------------------------------------------
// Kernel 2 (PDL): one warp per batch entry. Phase 1 (overlapped with the
// sweep via programmatic launch): index loads, random row gathers, dot
// product, bias loads. Then cudaGridDependencySynchronize() — sweep's zeros
// are globally visible. Phase 2: the scattered stores.
// Duplicate u/i/(u,i) across entries write identical values (benign race).
// ---------------------------------------------------------------------------
__global__ void __launch_bounds__(256)
mmf_scatter_pdl(const float* __restrict__ P,   // [U,K]
                const float* __restrict__ Q,   // [I,K]
                const float* __restrict__ bu,  // [U]
                const float* __restrict__ bi,  // [I]
                const int* __restrict__ uidx,  // [B] i32
                const int* __restrict__ iidx,  // [B] i32
                float* __restrict__ out) {
    int g    = blockIdx.x * blockDim.x + threadIdx.x;
    int e    = g >> 5;                         // entry = warp id
    int lane = g & 31;

    // ---- phase 1: all loads + compute (overlaps the sweep) ----
    int u = __ldg(&uidx[e]);
    int i = __ldg(&iidx[e]);

    const float2* pu = reinterpret_cast<const float2*>(P + (long long)u * K_DIM);
    const float2* qi = reinterpret_cast<const float2*>(Q + (long long)i * K_DIM);
    float2 a = __ldg(&pu[lane]);
    float2 b = __ldg(&qi[lane]);

    float s = warp_sum(fmaf(a.x, b.x, a.y * b.y));
    float bias_u = __ldg(&bu[u]);
    float bias_i = __ldg(&bi[i]);

    float2* uf  = reinterpret_cast<float2*>(out + OFF_UF + (long long)u * K_DIM);
    float2* ifr = reinterpret_cast<float2*>(out + OFF_IF + (long long)i * K_DIM);

    // ---- wait for the sweep's stores to be visible ----
    cudaGridDependencySynchronize();

    // ---- phase 2: scattered stores ----
    uf[lane]  = a;
    ifr[lane] = b;
    if (lane == 0) {
        out[OFF_UB + u] = bias_u;
        out[OFF_IB + i] = bias_i;
        out[(long long)u * I_DIM + i] = s + bias_u + bias_i;
    }
}

// ---------------------------------------------------------------------------
// Launch. inputs: P [U,K] f32, Q [I,K] f32, bu [U,1] f32, bi [I] f32,
// users_idx [B] int32, items_idx [B] int32
// ---------------------------------------------------------------------------
extern "C" void kernel_launch(void* const* d_in, const int* in_sizes, int n_in,
                              void* d_out, int out_size) {
    const float* P    = (const float*)d_in[0];
    const float* Q    = (const float*)d_in[1];
    const float* bu   = (const float*)d_in[2];
    const float* bi   = (const float*)d_in[3];
    const int*   uidx = (const int*)d_in[4];
    const int*   iidx = (const int*)d_in[5];
    float* out = (float*)d_out;

    // 1) zero everything (808 MB pure stores — the roofline)
    const long long n_total = (long long)out_size;   // 201,950,000
    const long long n4 = n_total / 4;                // divisible exactly
    const int zthreads = 256;
    const long long zblocks = (n4 + zthreads - 1) / zthreads;
    mmf_zero_kernel<<<(unsigned)zblocks, zthreads>>>((float4*)out, n4);

    // 2) scatter with programmatic dependent launch: prologue overlaps the
    //    sweep; stores gated by cudaGridDependencySynchronize().
    cudaLaunchConfig_t cfg = {};
    cfg.gridDim  = dim3((B_DIM * 32) / 256, 1, 1);   // 512 blocks
    cfg.blockDim = dim3(256, 1, 1);
    cudaLaunchAttribute attrs[1];
    attrs[0].id = cudaLaunchAttributeProgrammaticStreamSerialization;
    attrs[0].val.programmaticStreamSerializationAllowed = 1;
    cfg.attrs = attrs;
    cfg.numAttrs = 1;
    cudaLaunchKernelEx(&cfg, mmf_scatter_pdl, P, Q, bu, bi, uidx, iidx, out);
}

// round 9
// speedup vs baseline: 1.7409x; 1.7409x over previous
#include <cuda_runtime.h>
#include <cuda_bf16.h>
#include <cstdint>

// Problem constants
#define U_DIM 20000
#define I_DIM 10000
#define K_DIM 64
#define B_DIM 4096

// Output regions (floats), reference return order.
#define OFF_SHAT   0LL
#define N_SHAT     (200000000LL)                 // U*I
#define OFF_UF     (OFF_SHAT + N_SHAT)           // 200,000,000
#define N_UF       (1280000LL)
#define OFF_UB     (OFF_UF + N_UF)               // 201,280,000
#define N_UB       (20000LL)
#define OFF_IF     (OFF_UB + N_UB)               // 201,300,000
#define N_IF       (640000LL)
#define OFF_IB     (OFF_IF + N_IF)               // 201,940,000
#define N_IB       (10000LL)
#define N_TOTAL    (OFF_IB + N_IB)               // 201,950,000 (divisible by 4)

#define THREADS    256
#define N4_ALL     (N_TOTAL / 4)                 // 50,487,500 float4s
// zero blocks needed
#define NZ         ((int)((N4_ALL + THREADS - 1) / THREADS))   // 197,217

__device__ __forceinline__ float warp_sum(float s) {
    #pragma unroll
    for (int off = 16; off; off >>= 1)
        s += __shfl_xor_sync(0xffffffffu, s, off);
    return s;
}

// Spin until the word at p reads 0 (the sweep's zero-store has reached L2 —
// the coherence point) or already equals the target bits (duplicate entry
// patched it first), then store the value. If target bits are 0 the race is
// vacuously benign. Same-thread store after the observing load serializes
// after the zero-store at L2. No fences needed.
__device__ __forceinline__ void patch_scalar(float* p, float v) {
    unsigned tgt = __float_as_uint(v);
    unsigned x;
    do {
        asm volatile("ld.global.cv.b32 %0, [%1];" : "=r"(x) : "l"(p));
        if (x == 0u || x == tgt) break;
        __nanosleep(32);
    } while (true);
    asm volatile("st.global.b32 [%0], %1;" :: "l"(p), "r"(tgt) : "memory");
}

// ---------------------------------------------------------------------------
// Single fused kernel.
//   bid <  NZ : pure float4 zero store (identical to the proven 7.27 TB/s
//               sweep — no loads, no fences, no atomics).
//   bid >= NZ : patch block, one warp per batch entry, scheduled in the last
//               wave. Gathers rows, computes dot, then patches each output
//               scalar via spin-observe-store (see patch_scalar).
// ---------------------------------------------------------------------------
__global__ void __launch_bounds__(THREADS)
mmf_fused(const float* __restrict__ P,   // [U,K]
          const float* __restrict__ Q,   // [I,K]
          const float* __restrict__ bu,  // [U]
          const float* __restrict__ bi,  // [I]
          const int* __restrict__ uidx,  // [B] i32
          const int* __restrict__ iidx,  // [B] i32
          float* __restrict__ out,
          long long n4) {
    const int bid = blockIdx.x;

    if (bid < NZ) {
        // ---------------- zero path: pure fire-and-forget stores ----------
        long long idx = (long long)bid * THREADS + threadIdx.x;
        if (idx < n4) {
            reinterpret_cast<float4*>(out)[idx] =
                make_float4(0.f, 0.f, 0.f, 0.f);
        }
        return;
    }

    // ---------------- patch path: 4096 blocks, warp 0 of each -------------
    if (threadIdx.x >= 32) return;
    const int e    = bid - NZ;                 // batch entry
    const int lane = threadIdx.x;

    int u = __ldg(&uidx[e]);
    int i = __ldg(&iidx[e]);

    const float2* pu = reinterpret_cast<const float2*>(P + (long long)u * K_DIM);
    const float2* qi = reinterpret_cast<const float2*>(Q + (long long)i * K_DIM);
    float2 a = __ldg(&pu[lane]);               // elements 2*lane, 2*lane+1
    float2 b = __ldg(&qi[lane]);

    float s = warp_sum(fmaf(a.x, b.x, a.y * b.y));
    float bias_u = __ldg(&bu[u]);
    float bias_i = __ldg(&bi[i]);

    // masked factor rows
    float* uf  = out + OFF_UF + (long long)u * K_DIM;
    float* ifr = out + OFF_IF + (long long)i * K_DIM;
    patch_scalar(&uf[2 * lane],     a.x);
    patch_scalar(&uf[2 * lane + 1], a.y);
    patch_scalar(&ifr[2 * lane],     b.x);
    patch_scalar(&ifr[2 * lane + 1], b.y);

    if (lane == 0) {
        patch_scalar(&out[OFF_UB + u], bias_u);
        patch_scalar(&out[OFF_IB + i], bias_i);
        patch_scalar(&out[(long long)u * I_DIM + i], s + bias_u + bias_i);
    }
}

// ---------------------------------------------------------------------------
// Launch. inputs: P [U,K] f32, Q [I,K] f32, bu [U,1] f32, bi [I] f32,
// users_idx [B] int32, items_idx [B] int32
// ---------------------------------------------------------------------------
extern "C" void kernel_launch(void* const* d_in, const int* in_sizes, int n_in,
                              void* d_out, int out_size) {
    const float* P    = (const float*)d_in[0];
    const float* Q    = (const float*)d_in[1];
    const float* bu   = (const float*)d_in[2];
    const float* bi   = (const float*)d_in[3];
    const int*   uidx = (const int*)d_in[4];
    const int*   iidx = (const int*)d_in[5];
    float* out = (float*)d_out;

    const long long n4 = (long long)out_size / 4;    // 50,487,500 (exact)
    const int blocks = NZ + B_DIM;                   // zero blocks + patch blocks
    mmf_fused<<<blocks, THREADS>>>(P, Q, bu, bi, uidx, iidx, out, n4);
}

// round 10
// speedup vs baseline: 1.8311x; 1.0518x over previous
#include <cuda_runtime.h>
#include <cuda_bf16.h>
#include <cstdint>

// Problem constants
#define U_DIM 20000
#define I_DIM 10000
#define K_DIM 64
#define B_DIM 4096

// Output regions (floats), reference return order.
#define OFF_SHAT   0LL
#define N_SHAT     (200000000LL)                 // U*I
#define OFF_UF     (OFF_SHAT + N_SHAT)           // 200,000,000
#define N_UF       (1280000LL)
#define OFF_UB     (OFF_UF + N_UF)               // 201,280,000
#define N_UB       (20000LL)
#define OFF_IF     (OFF_UB + N_UB)               // 201,300,000
#define N_IF       (640000LL)
#define OFF_IB     (OFF_IF + N_IF)               // 201,940,000
#define N_IB       (10000LL)
#define N_TOTAL    (OFF_IB + N_IB)               // 201,950,000 (divisible by 4)

// ---------------------------------------------------------------------------
// Kernel 1: zero the whole output. PURE fire-and-forget float4 stores — no
// loads, no fences, no atomics, and crucially NO explicit PDL trigger
// (R8 showed GRIDDEPCONTROL.LAUNCH_DEPENDENTS has per-thread release
// semantics and halves store bandwidth). With no explicit trigger, the
// dependent kernel launches at completion, overlapping our epilogue.
// Proven 7.27 TB/s shape — do not touch.
// ---------------------------------------------------------------------------
__global__ void mmf_zero_kernel(float4* __restrict__ out, long long n4) {
    long long idx = (long long)blockIdx.x * blockDim.x + threadIdx.x;
    if (idx < n4) {
        out[idx] = make_float4(0.f, 0.f, 0.f, 0.f);
    }
}

__device__ __forceinline__ float warp_sum(float s) {
    #pragma unroll
    for (int off = 16; off; off >>= 1)
        s += __shfl_xor_sync(0xffffffffu, s, off);
    return s;
}

// ---------------------------------------------------------------------------
// Kernel 2 (PDL, implicit trigger): one warp per batch entry. Phase 1
// (overlaps the sweep's epilogue + launch ramp): index loads, random row
// gathers, dot product, bias loads. cudaGridDependencySynchronize() then
// guarantees the sweep's zeros are visible. Phase 2: scattered stores.
// Duplicate u/i/(u,i) across entries write identical values (benign race).
// ---------------------------------------------------------------------------
__global__ void __launch_bounds__(256)
mmf_scatter_pdl(const float* __restrict__ P,   // [U,K]
                const float* __restrict__ Q,   // [I,K]
                const float* __restrict__ bu,  // [U]
                const float* __restrict__ bi,  // [I]
                const int* __restrict__ uidx,  // [B] i32
                const int* __restrict__ iidx,  // [B] i32
                float* __restrict__ out) {
    int g    = blockIdx.x * blockDim.x + threadIdx.x;
    int e    = g >> 5;                         // entry = warp id
    int lane = g & 31;

    // ---- phase 1: all loads + compute (overlaps primary epilogue) ----
    int u = __ldg(&uidx[e]);
    int i = __ldg(&iidx[e]);

    const float2* pu = reinterpret_cast<const float2*>(P + (long long)u * K_DIM);
    const float2* qi = reinterpret_cast<const float2*>(Q + (long long)i * K_DIM);
    float2 a = __ldg(&pu[lane]);
    float2 b = __ldg(&qi[lane]);

    float s = warp_sum(fmaf(a.x, b.x, a.y * b.y));
    float bias_u = __ldg(&bu[u]);
    float bias_i = __ldg(&bi[i]);

    float2* uf  = reinterpret_cast<float2*>(out + OFF_UF + (long long)u * K_DIM);
    float2* ifr = reinterpret_cast<float2*>(out + OFF_IF + (long long)i * K_DIM);

    // ---- wait for the sweep's stores to be globally visible ----
    cudaGridDependencySynchronize();

    // ---- phase 2: scattered stores ----
    uf[lane]  = a;
    ifr[lane] = b;
    if (lane == 0) {
        out[OFF_UB + u] = bias_u;
        out[OFF_IB + i] = bias_i;
        out[(long long)u * I_DIM + i] = s + bias_u + bias_i;
    }
}

// ---------------------------------------------------------------------------
// Launch. inputs: P [U,K] f32, Q [I,K] f32, bu [U,1] f32, bi [I] f32,
// users_idx [B] int32, items_idx [B] int32
// ---------------------------------------------------------------------------
extern "C" void kernel_launch(void* const* d_in, const int* in_sizes, int n_in,
                              void* d_out, int out_size) {
    const float* P    = (const float*)d_in[0];
    const float* Q    = (const float*)d_in[1];
    const float* bu   = (const float*)d_in[2];
    const float* bi   = (const float*)d_in[3];
    const int*   uidx = (const int*)d_in[4];
    const int*   iidx = (const int*)d_in[5];
    float* out = (float*)d_out;

    // 1) zero everything (808 MB pure stores — the roofline, untouched)
    const long long n_total = (long long)out_size;   // 201,950,000
    const long long n4 = n_total / 4;                // divides exactly
    const int zthreads = 256;
    const long long zblocks = (n4 + zthreads - 1) / zthreads;
    mmf_zero_kernel<<<(unsigned)zblocks, zthreads>>>((float4*)out, n4);

    // 2) scatter with PDL (implicit trigger): prologue overlaps the sweep's
    //    epilogue; stores gated by cudaGridDependencySynchronize().
    cudaLaunchConfig_t cfg = {};
    cfg.gridDim  = dim3((B_DIM * 32) / 256, 1, 1);   // 512 blocks
    cfg.blockDim = dim3(256, 1, 1);
    cudaLaunchAttribute attrs[1];
    attrs[0].id = cudaLaunchAttributeProgrammaticStreamSerialization;
    attrs[0].val.programmaticStreamSerializationAllowed = 1;
    cfg.attrs = attrs;
    cfg.numAttrs = 1;
    cudaLaunchKernelEx(&cfg, mmf_scatter_pdl, P, Q, bu, bi, uidx, iidx, out);
}